// round 1
// baseline (speedup 1.0000x reference)
#include <cuda_runtime.h>

#define B_   4
#define T_   2048
#define H_   16
#define D_   64
#define INNER_ 1024
#define DM_  1024
#define KPROJ 512

// Scratch: [B, H, T, D] layout for q/k/v/attention-out. Device globals (no alloc).
__device__ float g_q [(size_t)B_*H_*T_*D_];
__device__ float g_k [(size_t)B_*H_*T_*D_];
__device__ float g_v [(size_t)B_*H_*T_*D_];
__device__ float g_ao[(size_t)B_*H_*T_*D_];

// ---------------------------------------------------------------------------
// Projection GEMM: [8192 x 512] (slice of x) @ [512 x 1024] (W) -> [B,H,T,D]
// which: 0=Q (x_pos, Wq), 1=K (x_pos, Wk), 2=V (x_tok, Wv)
// Tiles: BM=64, BN=64, BK=16, 256 threads, 4x4 microtile per thread.
// ---------------------------------------------------------------------------
__global__ __launch_bounds__(256) void proj_gemm(const float* __restrict__ x,
                                                 const float* __restrict__ W,
                                                 int which) {
    __shared__ float As[16 * 64];   // As[k][m]
    __shared__ float Bs[16 * 64];   // Bs[k][n]

    float* outp = (which == 0) ? g_q : (which == 1) ? g_k : g_v;
    const int coloff = (which == 2) ? 0 : 512;

    const int tid = threadIdx.x;
    const int tx = tid & 15, ty = tid >> 4;
    const int m0 = blockIdx.y * 64, n0 = blockIdx.x * 64;

    // Loader coords
    const int am  = tid >> 2, ak4 = tid & 3;    // A: 64 rows x 4 float4
    const int bk  = tid >> 4, bn4 = tid & 15;   // B: 16 rows x 16 float4

    float acc[4][4] = {};

    for (int k0 = 0; k0 < KPROJ; k0 += 16) {
        float4 av = *(const float4*)(x + (size_t)(m0 + am) * DM_ + coloff + k0 + ak4 * 4);
        float4 bv = *(const float4*)(W + (size_t)(k0 + bk) * INNER_ + n0 + bn4 * 4);
        As[(ak4 * 4 + 0) * 64 + am] = av.x;
        As[(ak4 * 4 + 1) * 64 + am] = av.y;
        As[(ak4 * 4 + 2) * 64 + am] = av.z;
        As[(ak4 * 4 + 3) * 64 + am] = av.w;
        *(float4*)(Bs + bk * 64 + bn4 * 4) = bv;
        __syncthreads();

        #pragma unroll
        for (int kk = 0; kk < 16; ++kk) {
            float4 a = *(const float4*)(As + kk * 64 + ty * 4);
            float4 b = *(const float4*)(Bs + kk * 64 + tx * 4);
            acc[0][0] += a.x * b.x; acc[0][1] += a.x * b.y;
            acc[0][2] += a.x * b.z; acc[0][3] += a.x * b.w;
            acc[1][0] += a.y * b.x; acc[1][1] += a.y * b.y;
            acc[1][2] += a.y * b.z; acc[1][3] += a.y * b.w;
            acc[2][0] += a.z * b.x; acc[2][1] += a.z * b.y;
            acc[2][2] += a.z * b.z; acc[2][3] += a.z * b.w;
            acc[3][0] += a.w * b.x; acc[3][1] += a.w * b.y;
            acc[3][2] += a.w * b.z; acc[3][3] += a.w * b.w;
        }
        __syncthreads();
    }

    // Epilogue: scatter to [B,H,T,D]. h is constant per block (BN==D).
    const int h = n0 >> 6;
    const int d0 = tx * 4;
    #pragma unroll
    for (int i = 0; i < 4; ++i) {
        int m = m0 + ty * 4 + i;
        int b = m >> 11;         // /T_
        int t = m & (T_ - 1);
        float4 v = make_float4(acc[i][0], acc[i][1], acc[i][2], acc[i][3]);
        *(float4*)(outp + (((size_t)b * H_ + h) * T_ + t) * D_ + d0) = v;
    }
}

// ---------------------------------------------------------------------------
// Flash attention (causal), fp32. One query row per thread, 128 rows/block.
// K/V tiles of 64 keys in smem; online softmax with 16-key chunking.
// ---------------------------------------------------------------------------
__global__ __launch_bounds__(128) void flash_attn() {
    const int bh  = blockIdx.y;                 // 0..63  (b*H + h)
    const int q0  = blockIdx.x * 128;
    const int tid = threadIdx.x;
    const int r   = q0 + tid;                   // this thread's query row
    const float scale = 0.125f;                 // 1/sqrt(64)

    float q[64], acc[64];
    {
        const float4* qr = (const float4*)(g_q + ((size_t)bh * T_ + r) * D_);
        #pragma unroll
        for (int d4 = 0; d4 < 16; ++d4) {
            float4 v = qr[d4];
            q[d4 * 4 + 0] = v.x * scale;
            q[d4 * 4 + 1] = v.y * scale;
            q[d4 * 4 + 2] = v.z * scale;
            q[d4 * 4 + 3] = v.w * scale;
        }
    }
    #pragma unroll
    for (int d = 0; d < 64; ++d) acc[d] = 0.f;
    float m_i = -1e30f, l_i = 0.f;

    __shared__ float Ks[64 * 64];
    __shared__ float Vs[64 * 64];

    const int nkt = blockIdx.x * 2 + 2;         // key tiles covering causal range
    for (int kt = 0; kt < nkt; ++kt) {
        __syncthreads();
        const float4* Kg = (const float4*)(g_k + ((size_t)bh * T_ + kt * 64) * D_);
        const float4* Vg = (const float4*)(g_v + ((size_t)bh * T_ + kt * 64) * D_);
        #pragma unroll
        for (int i = 0; i < 8; ++i) {
            ((float4*)Ks)[i * 128 + tid] = Kg[i * 128 + tid];
            ((float4*)Vs)[i * 128 + tid] = Vg[i * 128 + tid];
        }
        __syncthreads();

        int kmax = r - kt * 64 + 1;             // # valid keys in this tile
        if (kmax > 64) kmax = 64;
        for (int j0 = 0; j0 < kmax; j0 += 16) {
            float s[16];
            float mx = -1e30f;
            #pragma unroll
            for (int jj = 0; jj < 16; ++jj) {
                int j = j0 + jj;
                const float4* kr = (const float4*)(Ks + j * 64);
                float sum = 0.f;
                #pragma unroll
                for (int d4 = 0; d4 < 16; ++d4) {
                    float4 kv = kr[d4];
                    sum += q[d4 * 4 + 0] * kv.x + q[d4 * 4 + 1] * kv.y
                         + q[d4 * 4 + 2] * kv.z + q[d4 * 4 + 3] * kv.w;
                }
                if (j >= kmax) sum = -1e30f;    // causal mask inside boundary tile
                s[jj] = sum;
                mx = fmaxf(mx, sum);
            }
            float m_new = fmaxf(m_i, mx);
            float corr  = __expf(m_i - m_new);
            l_i *= corr;
            #pragma unroll
            for (int d = 0; d < 64; ++d) acc[d] *= corr;
            #pragma unroll
            for (int jj = 0; jj < 16; ++jj) {
                float p = __expf(s[jj] - m_new);
                l_i += p;
                const float4* vr = (const float4*)(Vs + (j0 + jj) * 64);
                #pragma unroll
                for (int d4 = 0; d4 < 16; ++d4) {
                    float4 vv = vr[d4];
                    acc[d4 * 4 + 0] += p * vv.x;
                    acc[d4 * 4 + 1] += p * vv.y;
                    acc[d4 * 4 + 2] += p * vv.z;
                    acc[d4 * 4 + 3] += p * vv.w;
                }
            }
            m_i = m_new;
        }
    }

    const float inv = 1.f / l_i;
    float4* orw = (float4*)(g_ao + ((size_t)bh * T_ + r) * D_);
    #pragma unroll
    for (int d4 = 0; d4 < 16; ++d4) {
        orw[d4] = make_float4(acc[d4 * 4 + 0] * inv, acc[d4 * 4 + 1] * inv,
                              acc[d4 * 4 + 2] * inv, acc[d4 * 4 + 3] * inv);
    }
}

// ---------------------------------------------------------------------------
// Output GEMM: gather A from g_ao ([B,H,T,D] -> [m, k] with k = h*64+d),
// [8192 x 1024] @ Wo [1024 x 1024] -> out [8192 x 1024]
// ---------------------------------------------------------------------------
__global__ __launch_bounds__(256) void out_gemm(const float* __restrict__ Wo,
                                                float* __restrict__ out) {
    __shared__ float As[16 * 64];
    __shared__ float Bs[16 * 64];

    const int tid = threadIdx.x;
    const int tx = tid & 15, ty = tid >> 4;
    const int m0 = blockIdx.y * 64, n0 = blockIdx.x * 64;

    const int am  = tid >> 2, ak4 = tid & 3;
    const int bk  = tid >> 4, bn4 = tid & 15;

    const int m  = m0 + am;
    const int bb = m >> 11;
    const int t  = m & (T_ - 1);

    float acc[4][4] = {};

    for (int k0 = 0; k0 < INNER_; k0 += 16) {
        int kg = k0 + ak4 * 4;
        int h  = kg >> 6;
        int dd = kg & 63;
        float4 av = *(const float4*)(g_ao + (((size_t)bb * H_ + h) * T_ + t) * D_ + dd);
        float4 bv = *(const float4*)(Wo + (size_t)(k0 + bk) * DM_ + n0 + bn4 * 4);
        As[(ak4 * 4 + 0) * 64 + am] = av.x;
        As[(ak4 * 4 + 1) * 64 + am] = av.y;
        As[(ak4 * 4 + 2) * 64 + am] = av.z;
        As[(ak4 * 4 + 3) * 64 + am] = av.w;
        *(float4*)(Bs + bk * 64 + bn4 * 4) = bv;
        __syncthreads();

        #pragma unroll
        for (int kk = 0; kk < 16; ++kk) {
            float4 a = *(const float4*)(As + kk * 64 + ty * 4);
            float4 b = *(const float4*)(Bs + kk * 64 + tx * 4);
            acc[0][0] += a.x * b.x; acc[0][1] += a.x * b.y;
            acc[0][2] += a.x * b.z; acc[0][3] += a.x * b.w;
            acc[1][0] += a.y * b.x; acc[1][1] += a.y * b.y;
            acc[1][2] += a.y * b.z; acc[1][3] += a.y * b.w;
            acc[2][0] += a.z * b.x; acc[2][1] += a.z * b.y;
            acc[2][2] += a.z * b.z; acc[2][3] += a.z * b.w;
            acc[3][0] += a.w * b.x; acc[3][1] += a.w * b.y;
            acc[3][2] += a.w * b.z; acc[3][3] += a.w * b.w;
        }
        __syncthreads();
    }

    #pragma unroll
    for (int i = 0; i < 4; ++i) {
        int mr = m0 + ty * 4 + i;
        float4 v = make_float4(acc[i][0], acc[i][1], acc[i][2], acc[i][3]);
        *(float4*)(out + (size_t)mr * DM_ + n0 + tx * 4) = v;
    }
}

// ---------------------------------------------------------------------------
extern "C" void kernel_launch(void* const* d_in, const int* in_sizes, int n_in,
                              void* d_out, int out_size) {
    const float* x  = (const float*)d_in[0];
    const float* Wq = (const float*)d_in[1];
    const float* Wk = (const float*)d_in[2];
    const float* Wv = (const float*)d_in[3];
    const float* Wo = (const float*)d_in[4];
    float* out = (float*)d_out;

    dim3 gg(INNER_ / 64, (B_ * T_) / 64);    // 16 x 128
    proj_gemm<<<gg, 256>>>(x, Wq, 0);
    proj_gemm<<<gg, 256>>>(x, Wk, 1);
    proj_gemm<<<gg, 256>>>(x, Wv, 2);
    flash_attn<<<dim3(T_ / 128, B_ * H_), 128>>>();
    out_gemm<<<gg, 256>>>(Wo, out);
}

// round 3
// speedup vs baseline: 3.4186x; 3.4186x over previous
#include <cuda_runtime.h>
#include <cstdint>

#define B_     4
#define T_     2048
#define H_     16
#define D_     64
#define INNER_ 1024
#define DM_    1024
#define KPROJ  512

// Scratch: [B, H, T, D] layout. Device globals (no allocation).
__device__ float g_q [(size_t)B_*H_*T_*D_];
__device__ float g_k [(size_t)B_*H_*T_*D_];
__device__ float g_v [(size_t)B_*H_*T_*D_];
__device__ float g_ao[(size_t)B_*H_*T_*D_];

// ---------------------------------------------------------------------------
// tf32 helpers
// ---------------------------------------------------------------------------
__device__ __forceinline__ uint32_t f2tf(float x) {
    uint32_t r;
    asm("cvt.rna.tf32.f32 %0, %1;" : "=r"(r) : "f"(x));
    return r;
}
__device__ __forceinline__ float f2tf_f(float x) {
    return __uint_as_float(f2tf(x));
}
__device__ __forceinline__ void mma8(float& c0, float& c1, float& c2, float& c3,
                                     uint32_t a0, uint32_t a1, uint32_t a2, uint32_t a3,
                                     uint32_t b0, uint32_t b1) {
    asm volatile(
        "mma.sync.aligned.m16n8k8.row.col.f32.tf32.tf32.f32 "
        "{%0,%1,%2,%3},{%4,%5,%6,%7},{%8,%9},{%0,%1,%2,%3};"
        : "+f"(c0), "+f"(c1), "+f"(c2), "+f"(c3)
        : "r"(a0), "r"(a1), "r"(a2), "r"(a3), "r"(b0), "r"(b1));
}

// ---------------------------------------------------------------------------
// tf32 GEMM. mode: 0=Q proj, 1=K proj, 2=V proj, 3=output GEMM.
// C[M,N] = A[M,K] @ W[K,N].  BM=128, BN=64, BK=32, 256 thr (8 warps, 32x32 each)
// mode 3 reads its A matrix from g_ao (gathered [B,H,T,D] -> [m,k]).
// ---------------------------------------------------------------------------
__global__ __launch_bounds__(256) void mm_tf32(const float* __restrict__ A,
                                               const float* __restrict__ W,
                                               float* __restrict__ Cout,
                                               int mode, int Ktot) {
    __shared__ float As[128][36];   // [m][k], pad -> bank (4g+t) conflict-free
    __shared__ float Bs[32][72];    // [k][n], pad -> bank (8t+g) conflict-free

    const int tid  = threadIdx.x;
    const int warp = tid >> 5, lane = tid & 31;
    const int g = lane >> 2, t = lane & 3;
    const int wm = warp >> 1, wn = warp & 1;
    const int m0 = blockIdx.y * 128, n0 = blockIdx.x * 64;
    const int coloff = (mode == 2) ? 0 : 512;

    float c[2][4][4];
    #pragma unroll
    for (int i = 0; i < 2; ++i)
        #pragma unroll
        for (int j = 0; j < 4; ++j)
            #pragma unroll
            for (int e = 0; e < 4; ++e) c[i][j][e] = 0.f;

    for (int k0 = 0; k0 < Ktot; k0 += 32) {
        // --- stage A tile (128x32), convert to tf32 on store ---
        #pragma unroll
        for (int i = 0; i < 4; ++i) {
            int idx = tid + 256 * i;
            int r = idx >> 3, c4 = idx & 7;
            const float* src;
            if (mode < 3) {
                src = A + (size_t)(m0 + r) * DM_ + coloff + k0 + c4 * 4;
            } else {
                int m = m0 + r, b = m >> 11, tt = m & (T_ - 1);
                int k = k0 + c4 * 4, h = k >> 6, d = k & 63;
                src = g_ao + (((size_t)b * H_ + h) * T_ + tt) * D_ + d;
            }
            float4 v = *(const float4*)src;
            As[r][c4 * 4 + 0] = f2tf_f(v.x);
            As[r][c4 * 4 + 1] = f2tf_f(v.y);
            As[r][c4 * 4 + 2] = f2tf_f(v.z);
            As[r][c4 * 4 + 3] = f2tf_f(v.w);
        }
        // --- stage B tile (32x64) ---
        #pragma unroll
        for (int i = 0; i < 2; ++i) {
            int idx = tid + 256 * i;
            int r = idx >> 4, c4 = idx & 15;
            float4 v = *(const float4*)(W + (size_t)(k0 + r) * 1024 + n0 + c4 * 4);
            Bs[r][c4 * 4 + 0] = f2tf_f(v.x);
            Bs[r][c4 * 4 + 1] = f2tf_f(v.y);
            Bs[r][c4 * 4 + 2] = f2tf_f(v.z);
            Bs[r][c4 * 4 + 3] = f2tf_f(v.w);
        }
        __syncthreads();

        #pragma unroll
        for (int s = 0; s < 4; ++s) {
            uint32_t a[2][4], b[4][2];
            #pragma unroll
            for (int mf = 0; mf < 2; ++mf) {
                int rr = wm * 32 + mf * 16;
                a[mf][0] = __float_as_uint(As[rr + g    ][s * 8 + t    ]);
                a[mf][1] = __float_as_uint(As[rr + g + 8][s * 8 + t    ]);
                a[mf][2] = __float_as_uint(As[rr + g    ][s * 8 + t + 4]);
                a[mf][3] = __float_as_uint(As[rr + g + 8][s * 8 + t + 4]);
            }
            #pragma unroll
            for (int nf = 0; nf < 4; ++nf) {
                int cc = wn * 32 + nf * 8 + g;
                b[nf][0] = __float_as_uint(Bs[s * 8 + t    ][cc]);
                b[nf][1] = __float_as_uint(Bs[s * 8 + t + 4][cc]);
            }
            #pragma unroll
            for (int mf = 0; mf < 2; ++mf)
                #pragma unroll
                for (int nf = 0; nf < 4; ++nf)
                    mma8(c[mf][nf][0], c[mf][nf][1], c[mf][nf][2], c[mf][nf][3],
                         a[mf][0], a[mf][1], a[mf][2], a[mf][3],
                         b[nf][0], b[nf][1]);
        }
        __syncthreads();
    }

    // --- epilogue ---
    if (mode < 3) {
        float* outp = (mode == 0) ? g_q : (mode == 1) ? g_k : g_v;
        const int h = n0 >> 6;
        #pragma unroll
        for (int mf = 0; mf < 2; ++mf) {
            #pragma unroll
            for (int nf = 0; nf < 4; ++nf) {
                int row = m0 + wm * 32 + mf * 16 + g;
                int d   = wn * 32 + nf * 8 + 2 * t;
                int b = row >> 11, tt = row & (T_ - 1);
                *(float2*)(outp + (((size_t)b * H_ + h) * T_ + tt) * D_ + d) =
                    make_float2(c[mf][nf][0], c[mf][nf][1]);
                row += 8; b = row >> 11; tt = row & (T_ - 1);
                *(float2*)(outp + (((size_t)b * H_ + h) * T_ + tt) * D_ + d) =
                    make_float2(c[mf][nf][2], c[mf][nf][3]);
            }
        }
    } else {
        #pragma unroll
        for (int mf = 0; mf < 2; ++mf) {
            #pragma unroll
            for (int nf = 0; nf < 4; ++nf) {
                int row = m0 + wm * 32 + mf * 16 + g;
                int cc  = n0 + wn * 32 + nf * 8 + 2 * t;
                *(float2*)(Cout + (size_t)row * DM_ + cc) =
                    make_float2(c[mf][nf][0], c[mf][nf][1]);
                *(float2*)(Cout + (size_t)(row + 8) * DM_ + cc) =
                    make_float2(c[mf][nf][2], c[mf][nf][3]);
            }
        }
    }
}

// ---------------------------------------------------------------------------
// Flash attention, tf32 mma. 64 queries/block, 4 warps (16 rows each).
// bufA: Q staging -> K tile -> P tile (aliased).  bufB: V tile.
// ---------------------------------------------------------------------------
__global__ __launch_bounds__(128) void attn_tf32() {
    __shared__ float bufA[64][68];  // stride 68: bank (4g+t) patterns conflict-free
    __shared__ float bufB[64][72];  // stride 72: bank (8t+g) patterns conflict-free

    const int tid = threadIdx.x, warp = tid >> 5, lane = tid & 31;
    const int g = lane >> 2, t = lane & 3;
    const int bh = blockIdx.y, qt = blockIdx.x, q0 = qt * 64;
    const float scale = 0.125f;  // 1/sqrt(64)

    // --- stage Q tile (scaled, tf32) ---
    const float* Qg = g_q + ((size_t)bh * T_ + q0) * D_;
    #pragma unroll
    for (int i = 0; i < 8; ++i) {
        int idx = tid + 128 * i;
        int r = idx >> 4, c4 = idx & 15;
        float4 v = *(const float4*)(Qg + r * 64 + c4 * 4);
        bufA[r][c4 * 4 + 0] = f2tf_f(v.x * scale);
        bufA[r][c4 * 4 + 1] = f2tf_f(v.y * scale);
        bufA[r][c4 * 4 + 2] = f2tf_f(v.z * scale);
        bufA[r][c4 * 4 + 3] = f2tf_f(v.w * scale);
    }
    __syncthreads();

    // Q A-fragments for all 8 k-slices (d = 64)
    uint32_t qa[8][4];
    #pragma unroll
    for (int s = 0; s < 8; ++s) {
        int rr = warp * 16;
        qa[s][0] = __float_as_uint(bufA[rr + g    ][s * 8 + t    ]);
        qa[s][1] = __float_as_uint(bufA[rr + g + 8][s * 8 + t    ]);
        qa[s][2] = __float_as_uint(bufA[rr + g    ][s * 8 + t + 4]);
        qa[s][3] = __float_as_uint(bufA[rr + g + 8][s * 8 + t + 4]);
    }

    float o[8][4];
    #pragma unroll
    for (int nf = 0; nf < 8; ++nf)
        #pragma unroll
        for (int e = 0; e < 4; ++e) o[nf][e] = 0.f;
    float mrow0 = -1e30f, mrow1 = -1e30f, lrow0 = 0.f, lrow1 = 0.f;

    const int row0 = q0 + warp * 16 + g;
    const int row1 = row0 + 8;

    for (int kt = 0; kt <= qt; ++kt) {
        __syncthreads();  // prev-iter P/V reads done before overwrite
        const float* Kg = g_k + ((size_t)bh * T_ + kt * 64) * D_;
        const float* Vg = g_v + ((size_t)bh * T_ + kt * 64) * D_;
        #pragma unroll
        for (int i = 0; i < 8; ++i) {
            int idx = tid + 128 * i;
            int r = idx >> 4, c4 = idx & 15;
            float4 kv = *(const float4*)(Kg + r * 64 + c4 * 4);
            bufA[r][c4 * 4 + 0] = f2tf_f(kv.x);
            bufA[r][c4 * 4 + 1] = f2tf_f(kv.y);
            bufA[r][c4 * 4 + 2] = f2tf_f(kv.z);
            bufA[r][c4 * 4 + 3] = f2tf_f(kv.w);
            float4 vv = *(const float4*)(Vg + r * 64 + c4 * 4);
            bufB[r][c4 * 4 + 0] = f2tf_f(vv.x);
            bufB[r][c4 * 4 + 1] = f2tf_f(vv.y);
            bufB[r][c4 * 4 + 2] = f2tf_f(vv.z);
            bufB[r][c4 * 4 + 3] = f2tf_f(vv.w);
        }
        __syncthreads();

        // --- S = Q @ K^T (16x64 per warp) ---
        float sc[8][4];
        #pragma unroll
        for (int nf = 0; nf < 8; ++nf)
            #pragma unroll
            for (int e = 0; e < 4; ++e) sc[nf][e] = 0.f;
        #pragma unroll
        for (int s = 0; s < 8; ++s) {
            #pragma unroll
            for (int nf = 0; nf < 8; ++nf) {
                uint32_t b0 = __float_as_uint(bufA[nf * 8 + g][s * 8 + t    ]);
                uint32_t b1 = __float_as_uint(bufA[nf * 8 + g][s * 8 + t + 4]);
                mma8(sc[nf][0], sc[nf][1], sc[nf][2], sc[nf][3],
                     qa[s][0], qa[s][1], qa[s][2], qa[s][3], b0, b1);
            }
        }

        // --- causal mask (diagonal tile only) ---
        if (kt == qt) {
            #pragma unroll
            for (int nf = 0; nf < 8; ++nf) {
                int col = kt * 64 + nf * 8 + 2 * t;
                if (col     > row0) sc[nf][0] = -1e30f;
                if (col + 1 > row0) sc[nf][1] = -1e30f;
                if (col     > row1) sc[nf][2] = -1e30f;
                if (col + 1 > row1) sc[nf][3] = -1e30f;
            }
        }

        // --- online softmax ---
        float mx0 = -1e30f, mx1 = -1e30f;
        #pragma unroll
        for (int nf = 0; nf < 8; ++nf) {
            mx0 = fmaxf(mx0, fmaxf(sc[nf][0], sc[nf][1]));
            mx1 = fmaxf(mx1, fmaxf(sc[nf][2], sc[nf][3]));
        }
        mx0 = fmaxf(mx0, __shfl_xor_sync(0xffffffffu, mx0, 1));
        mx0 = fmaxf(mx0, __shfl_xor_sync(0xffffffffu, mx0, 2));
        mx1 = fmaxf(mx1, __shfl_xor_sync(0xffffffffu, mx1, 1));
        mx1 = fmaxf(mx1, __shfl_xor_sync(0xffffffffu, mx1, 2));
        float mn0 = fmaxf(mrow0, mx0), mn1 = fmaxf(mrow1, mx1);
        float cor0 = __expf(mrow0 - mn0), cor1 = __expf(mrow1 - mn1);
        lrow0 *= cor0; lrow1 *= cor1;
        #pragma unroll
        for (int nf = 0; nf < 8; ++nf) {
            o[nf][0] *= cor0; o[nf][1] *= cor0;
            o[nf][2] *= cor1; o[nf][3] *= cor1;
        }
        #pragma unroll
        for (int nf = 0; nf < 8; ++nf) {
            float p0 = __expf(sc[nf][0] - mn0);
            float p1 = __expf(sc[nf][1] - mn0);
            float p2 = __expf(sc[nf][2] - mn1);
            float p3 = __expf(sc[nf][3] - mn1);
            lrow0 += p0 + p1; lrow1 += p2 + p3;
            sc[nf][0] = p0; sc[nf][1] = p1; sc[nf][2] = p2; sc[nf][3] = p3;
        }
        mrow0 = mn0; mrow1 = mn1;

        __syncthreads();  // all warps done reading K from bufA before P overwrite

        // --- store P (tf32) into bufA rows owned by this warp ---
        #pragma unroll
        for (int nf = 0; nf < 8; ++nf) {
            int rr = warp * 16 + g;
            *(float2*)&bufA[rr    ][nf * 8 + 2 * t] =
                make_float2(f2tf_f(sc[nf][0]), f2tf_f(sc[nf][1]));
            *(float2*)&bufA[rr + 8][nf * 8 + 2 * t] =
                make_float2(f2tf_f(sc[nf][2]), f2tf_f(sc[nf][3]));
        }
        __syncwarp();

        // --- O += P @ V ---
        #pragma unroll
        for (int s = 0; s < 8; ++s) {
            int rr = warp * 16;
            uint32_t pa0 = __float_as_uint(bufA[rr + g    ][s * 8 + t    ]);
            uint32_t pa1 = __float_as_uint(bufA[rr + g + 8][s * 8 + t    ]);
            uint32_t pa2 = __float_as_uint(bufA[rr + g    ][s * 8 + t + 4]);
            uint32_t pa3 = __float_as_uint(bufA[rr + g + 8][s * 8 + t + 4]);
            #pragma unroll
            for (int nf = 0; nf < 8; ++nf) {
                uint32_t b0 = __float_as_uint(bufB[s * 8 + t    ][nf * 8 + g]);
                uint32_t b1 = __float_as_uint(bufB[s * 8 + t + 4][nf * 8 + g]);
                mma8(o[nf][0], o[nf][1], o[nf][2], o[nf][3],
                     pa0, pa1, pa2, pa3, b0, b1);
            }
        }
    }

    // --- finalize ---
    lrow0 += __shfl_xor_sync(0xffffffffu, lrow0, 1);
    lrow0 += __shfl_xor_sync(0xffffffffu, lrow0, 2);
    lrow1 += __shfl_xor_sync(0xffffffffu, lrow1, 1);
    lrow1 += __shfl_xor_sync(0xffffffffu, lrow1, 2);
    float inv0 = 1.f / lrow0, inv1 = 1.f / lrow1;

    float* Og = g_ao + ((size_t)bh * T_ + q0 + warp * 16 + g) * D_;
    #pragma unroll
    for (int nf = 0; nf < 8; ++nf) {
        *(float2*)(Og + nf * 8 + 2 * t) =
            make_float2(o[nf][0] * inv0, o[nf][1] * inv0);
        *(float2*)(Og + 8 * D_ + nf * 8 + 2 * t) =
            make_float2(o[nf][2] * inv1, o[nf][3] * inv1);
    }
}

// ---------------------------------------------------------------------------
extern "C" void kernel_launch(void* const* d_in, const int* in_sizes, int n_in,
                              void* d_out, int out_size) {
    const float* x  = (const float*)d_in[0];
    const float* Wq = (const float*)d_in[1];
    const float* Wk = (const float*)d_in[2];
    const float* Wv = (const float*)d_in[3];
    const float* Wo = (const float*)d_in[4];
    float* out = (float*)d_out;

    dim3 gg(INNER_ / 64, (B_ * T_) / 128);   // 16 x 64
    mm_tf32<<<gg, 256>>>(x, Wq, nullptr, 0, KPROJ);
    mm_tf32<<<gg, 256>>>(x, Wk, nullptr, 1, KPROJ);
    mm_tf32<<<gg, 256>>>(x, Wv, nullptr, 2, KPROJ);
    attn_tf32<<<dim3(T_ / 64, B_ * H_), 128>>>();
    mm_tf32<<<gg, 256>>>(x /*unused*/, Wo, out, 3, INNER_);
}

// round 6
// speedup vs baseline: 3.4342x; 1.0046x over previous
#include <cuda_runtime.h>
#include <cstdint>

#define B_     4
#define T_     2048
#define H_     16
#define D_     64
#define INNER_ 1024
#define DM_    1024
#define KPROJ  512

// Scratch: [B, H, T, D] layout. Device globals (no allocation).
__device__ float g_q [(size_t)B_*H_*T_*D_];
__device__ float g_k [(size_t)B_*H_*T_*D_];
__device__ float g_v [(size_t)B_*H_*T_*D_];
__device__ float g_ao[(size_t)B_*H_*T_*D_];

// ---------------------------------------------------------------------------
// tf32 helpers
// ---------------------------------------------------------------------------
__device__ __forceinline__ uint32_t f2tf(float x) {
    uint32_t r;
    asm("cvt.rna.tf32.f32 %0, %1;" : "=r"(r) : "f"(x));
    return r;
}
__device__ __forceinline__ float f2tf_f(float x) {
    return __uint_as_float(f2tf(x));
}
__device__ __forceinline__ void mma8(float& c0, float& c1, float& c2, float& c3,
                                     uint32_t a0, uint32_t a1, uint32_t a2, uint32_t a3,
                                     uint32_t b0, uint32_t b1) {
    asm volatile(
        "mma.sync.aligned.m16n8k8.row.col.f32.tf32.tf32.f32 "
        "{%0,%1,%2,%3},{%4,%5,%6,%7},{%8,%9},{%0,%1,%2,%3};"
        : "+f"(c0), "+f"(c1), "+f"(c2), "+f"(c3)
        : "r"(a0), "r"(a1), "r"(a2), "r"(a3), "r"(b0), "r"(b1));
}

// ---------------------------------------------------------------------------
// tf32 GEMM. mode: 0=Q proj, 1=K proj, 2=V proj, 3=output GEMM (A from g_ao).
// C[M,N] = A[M,K] @ W[K,N].  BM=128, BN=128, BK=32, 256 thr.
// 8 warps as 4(m) x 2(n); warp tile 32x64 = 2 m-frags x 8 n-frags.
// ---------------------------------------------------------------------------
__global__ __launch_bounds__(256) void mm_tf32(const float* __restrict__ A,
                                               const float* __restrict__ W,
                                               float* __restrict__ Cout,
                                               int mode, int Ktot) {
    __shared__ float As[128][36];    // [m][k]; bank 4g+t conflict-free
    __shared__ float Bs[32][136];    // [k][n]; 136 % 32 == 8 -> bank 8t+g

    const int tid  = threadIdx.x;
    const int warp = tid >> 5, lane = tid & 31;
    const int g = lane >> 2, t = lane & 3;
    const int wm = warp >> 1, wn = warp & 1;
    const int m0 = blockIdx.y * 128, n0 = blockIdx.x * 128;
    const int coloff = (mode == 2) ? 0 : 512;

    float c[2][8][4];
    #pragma unroll
    for (int mf = 0; mf < 2; ++mf)
        #pragma unroll
        for (int nf = 0; nf < 8; ++nf)
            #pragma unroll
            for (int e = 0; e < 4; ++e) c[mf][nf][e] = 0.f;

    for (int k0 = 0; k0 < Ktot; k0 += 32) {
        // --- stage A tile (128x32) ---
        #pragma unroll
        for (int i = 0; i < 4; ++i) {
            int idx = tid + 256 * i;
            int r = idx >> 3, c4 = idx & 7;
            const float* src;
            if (mode < 3) {
                src = A + (size_t)(m0 + r) * DM_ + coloff + k0 + c4 * 4;
            } else {
                int m = m0 + r, b = m >> 11, tt = m & (T_ - 1);
                int k = k0 + c4 * 4, h = k >> 6, d = k & 63;
                src = g_ao + (((size_t)b * H_ + h) * T_ + tt) * D_ + d;
            }
            float4 v = *(const float4*)src;
            As[r][c4 * 4 + 0] = f2tf_f(v.x);
            As[r][c4 * 4 + 1] = f2tf_f(v.y);
            As[r][c4 * 4 + 2] = f2tf_f(v.z);
            As[r][c4 * 4 + 3] = f2tf_f(v.w);
        }
        // --- stage B tile (32x128) ---
        #pragma unroll
        for (int i = 0; i < 4; ++i) {
            int idx = tid + 256 * i;
            int r = idx >> 5, c4 = idx & 31;
            float4 v = *(const float4*)(W + (size_t)(k0 + r) * 1024 + n0 + c4 * 4);
            Bs[r][c4 * 4 + 0] = f2tf_f(v.x);
            Bs[r][c4 * 4 + 1] = f2tf_f(v.y);
            Bs[r][c4 * 4 + 2] = f2tf_f(v.z);
            Bs[r][c4 * 4 + 3] = f2tf_f(v.w);
        }
        __syncthreads();

        #pragma unroll
        for (int s = 0; s < 4; ++s) {
            uint32_t a[2][4];
            #pragma unroll
            for (int mf = 0; mf < 2; ++mf) {
                int rr = wm * 32 + mf * 16;
                a[mf][0] = __float_as_uint(As[rr + g    ][s * 8 + t    ]);
                a[mf][1] = __float_as_uint(As[rr + g + 8][s * 8 + t    ]);
                a[mf][2] = __float_as_uint(As[rr + g    ][s * 8 + t + 4]);
                a[mf][3] = __float_as_uint(As[rr + g + 8][s * 8 + t + 4]);
            }
            #pragma unroll
            for (int nf = 0; nf < 8; ++nf) {
                int cc = wn * 64 + nf * 8 + g;
                uint32_t b0 = __float_as_uint(Bs[s * 8 + t    ][cc]);
                uint32_t b1 = __float_as_uint(Bs[s * 8 + t + 4][cc]);
                mma8(c[0][nf][0], c[0][nf][1], c[0][nf][2], c[0][nf][3],
                     a[0][0], a[0][1], a[0][2], a[0][3], b0, b1);
                mma8(c[1][nf][0], c[1][nf][1], c[1][nf][2], c[1][nf][3],
                     a[1][0], a[1][1], a[1][2], a[1][3], b0, b1);
            }
        }
        __syncthreads();
    }

    // --- epilogue ---
    if (mode < 3) {
        float* outp = (mode == 0) ? g_q : (mode == 1) ? g_k : g_v;
        #pragma unroll
        for (int mf = 0; mf < 2; ++mf) {
            #pragma unroll
            for (int nf = 0; nf < 8; ++nf) {
                int col = n0 + wn * 64 + nf * 8 + 2 * t;
                int h = col >> 6, d = col & 63;
                int row = m0 + wm * 32 + mf * 16 + g;
                int b = row >> 11, tt = row & (T_ - 1);
                *(float2*)(outp + (((size_t)b * H_ + h) * T_ + tt) * D_ + d) =
                    make_float2(c[mf][nf][0], c[mf][nf][1]);
                row += 8; b = row >> 11; tt = row & (T_ - 1);
                *(float2*)(outp + (((size_t)b * H_ + h) * T_ + tt) * D_ + d) =
                    make_float2(c[mf][nf][2], c[mf][nf][3]);
            }
        }
    } else {
        #pragma unroll
        for (int mf = 0; mf < 2; ++mf) {
            #pragma unroll
            for (int nf = 0; nf < 8; ++nf) {
                int row = m0 + wm * 32 + mf * 16 + g;
                int cc  = n0 + wn * 64 + nf * 8 + 2 * t;
                *(float2*)(Cout + (size_t)row * DM_ + cc) =
                    make_float2(c[mf][nf][0], c[mf][nf][1]);
                *(float2*)(Cout + (size_t)(row + 8) * DM_ + cc) =
                    make_float2(c[mf][nf][2], c[mf][nf][3]);
            }
        }
    }
}

// ---------------------------------------------------------------------------
// Flash attention, tf32 mma. 128 queries/block, 4 warps, warp tile 32x64.
// Dynamic smem: Qs[128][68] | Ks[64][68] | Vs[64][72] | Ps[128][68]
// ---------------------------------------------------------------------------
#define ATTN_SMEM ((128*68 + 64*68 + 64*72 + 128*68) * 4)

__global__ __launch_bounds__(128) void attn_tf32() {
    extern __shared__ float sm[];
    float (*Qs)[68] = (float(*)[68])(sm);
    float (*Ks)[68] = (float(*)[68])(sm + 128 * 68);
    float (*Vs)[72] = (float(*)[72])(sm + 128 * 68 + 64 * 68);
    float (*Ps)[68] = (float(*)[68])(sm + 128 * 68 + 64 * 68 + 64 * 72);

    const int tid = threadIdx.x, warp = tid >> 5, lane = tid & 31;
    const int g = lane >> 2, t = lane & 3;
    const int bh = blockIdx.y, qb = blockIdx.x, q0 = qb * 128;
    const float scale = 0.125f;  // 1/sqrt(64)

    // --- stage Q tile (128x64, scaled, tf32) ---
    const float* Qg = g_q + ((size_t)bh * T_ + q0) * D_;
    #pragma unroll
    for (int i = 0; i < 16; ++i) {
        int idx = tid + 128 * i;
        int r = idx >> 4, c4 = idx & 15;
        float4 v = *(const float4*)(Qg + r * 64 + c4 * 4);
        Qs[r][c4 * 4 + 0] = f2tf_f(v.x * scale);
        Qs[r][c4 * 4 + 1] = f2tf_f(v.y * scale);
        Qs[r][c4 * 4 + 2] = f2tf_f(v.z * scale);
        Qs[r][c4 * 4 + 3] = f2tf_f(v.w * scale);
    }

    float o[2][8][4];
    #pragma unroll
    for (int mf = 0; mf < 2; ++mf)
        #pragma unroll
        for (int nf = 0; nf < 8; ++nf)
            #pragma unroll
            for (int e = 0; e < 4; ++e) o[mf][nf][e] = 0.f;
    float mr[4] = {-1e30f, -1e30f, -1e30f, -1e30f};
    float lr[4] = {0.f, 0.f, 0.f, 0.f};

    const int rbase = q0 + warp * 32;
    const int nkt = 2 * qb + 2;

    for (int kt = 0; kt < nkt; ++kt) {
        __syncthreads();   // prev-iter K/V reads done before overwrite
        const float* Kg = g_k + ((size_t)bh * T_ + kt * 64) * D_;
        const float* Vg = g_v + ((size_t)bh * T_ + kt * 64) * D_;
        #pragma unroll
        for (int i = 0; i < 8; ++i) {
            int idx = tid + 128 * i;
            int r = idx >> 4, c4 = idx & 15;
            float4 kv = *(const float4*)(Kg + r * 64 + c4 * 4);
            Ks[r][c4 * 4 + 0] = f2tf_f(kv.x);
            Ks[r][c4 * 4 + 1] = f2tf_f(kv.y);
            Ks[r][c4 * 4 + 2] = f2tf_f(kv.z);
            Ks[r][c4 * 4 + 3] = f2tf_f(kv.w);
            float4 vv = *(const float4*)(Vg + r * 64 + c4 * 4);
            Vs[r][c4 * 4 + 0] = f2tf_f(vv.x);
            Vs[r][c4 * 4 + 1] = f2tf_f(vv.y);
            Vs[r][c4 * 4 + 2] = f2tf_f(vv.z);
            Vs[r][c4 * 4 + 3] = f2tf_f(vv.w);
        }
        __syncthreads();

        // Skip tiles fully above the causal boundary for this warp's rows.
        if (kt * 64 > rbase + 31) continue;

        // --- S = Q @ K^T (32x64 per warp) ---
        float sc[2][8][4];
        #pragma unroll
        for (int mf = 0; mf < 2; ++mf)
            #pragma unroll
            for (int nf = 0; nf < 8; ++nf)
                #pragma unroll
                for (int e = 0; e < 4; ++e) sc[mf][nf][e] = 0.f;
        #pragma unroll
        for (int s = 0; s < 8; ++s) {
            uint32_t a[2][4];
            #pragma unroll
            for (int mf = 0; mf < 2; ++mf) {
                int rr = warp * 32 + mf * 16;
                a[mf][0] = __float_as_uint(Qs[rr + g    ][s * 8 + t    ]);
                a[mf][1] = __float_as_uint(Qs[rr + g + 8][s * 8 + t    ]);
                a[mf][2] = __float_as_uint(Qs[rr + g    ][s * 8 + t + 4]);
                a[mf][3] = __float_as_uint(Qs[rr + g + 8][s * 8 + t + 4]);
            }
            #pragma unroll
            for (int nf = 0; nf < 8; ++nf) {
                uint32_t b0 = __float_as_uint(Ks[nf * 8 + g][s * 8 + t    ]);
                uint32_t b1 = __float_as_uint(Ks[nf * 8 + g][s * 8 + t + 4]);
                mma8(sc[0][nf][0], sc[0][nf][1], sc[0][nf][2], sc[0][nf][3],
                     a[0][0], a[0][1], a[0][2], a[0][3], b0, b1);
                mma8(sc[1][nf][0], sc[1][nf][1], sc[1][nf][2], sc[1][nf][3],
                     a[1][0], a[1][1], a[1][2], a[1][3], b0, b1);
            }
        }

        // --- causal mask (boundary tiles only) ---
        if (kt >= 2 * qb) {
            #pragma unroll
            for (int mf = 0; mf < 2; ++mf) {
                int row0 = rbase + mf * 16 + g;
                int row1 = row0 + 8;
                #pragma unroll
                for (int nf = 0; nf < 8; ++nf) {
                    int col = kt * 64 + nf * 8 + 2 * t;
                    if (col     > row0) sc[mf][nf][0] = -1e30f;
                    if (col + 1 > row0) sc[mf][nf][1] = -1e30f;
                    if (col     > row1) sc[mf][nf][2] = -1e30f;
                    if (col + 1 > row1) sc[mf][nf][3] = -1e30f;
                }
            }
        }

        // --- online softmax (4 row-groups per thread) ---
        float mx[4] = {-1e30f, -1e30f, -1e30f, -1e30f};
        #pragma unroll
        for (int mf = 0; mf < 2; ++mf)
            #pragma unroll
            for (int nf = 0; nf < 8; ++nf) {
                mx[mf * 2 + 0] = fmaxf(mx[mf * 2 + 0], fmaxf(sc[mf][nf][0], sc[mf][nf][1]));
                mx[mf * 2 + 1] = fmaxf(mx[mf * 2 + 1], fmaxf(sc[mf][nf][2], sc[mf][nf][3]));
            }
        #pragma unroll
        for (int rix = 0; rix < 4; ++rix) {
            mx[rix] = fmaxf(mx[rix], __shfl_xor_sync(0xffffffffu, mx[rix], 1));
            mx[rix] = fmaxf(mx[rix], __shfl_xor_sync(0xffffffffu, mx[rix], 2));
        }
        float mn[4], cor[4];
        #pragma unroll
        for (int rix = 0; rix < 4; ++rix) {
            mn[rix]  = fmaxf(mr[rix], mx[rix]);
            cor[rix] = __expf(mr[rix] - mn[rix]);
            lr[rix] *= cor[rix];
            mr[rix]  = mn[rix];
        }
        #pragma unroll
        for (int mf = 0; mf < 2; ++mf)
            #pragma unroll
            for (int nf = 0; nf < 8; ++nf) {
                o[mf][nf][0] *= cor[mf * 2 + 0]; o[mf][nf][1] *= cor[mf * 2 + 0];
                o[mf][nf][2] *= cor[mf * 2 + 1]; o[mf][nf][3] *= cor[mf * 2 + 1];
            }
        #pragma unroll
        for (int mf = 0; mf < 2; ++mf)
            #pragma unroll
            for (int nf = 0; nf < 8; ++nf) {
                float p0 = __expf(sc[mf][nf][0] - mn[mf * 2 + 0]);
                float p1 = __expf(sc[mf][nf][1] - mn[mf * 2 + 0]);
                float p2 = __expf(sc[mf][nf][2] - mn[mf * 2 + 1]);
                float p3 = __expf(sc[mf][nf][3] - mn[mf * 2 + 1]);
                lr[mf * 2 + 0] += p0 + p1;
                lr[mf * 2 + 1] += p2 + p3;
                sc[mf][nf][0] = p0; sc[mf][nf][1] = p1;
                sc[mf][nf][2] = p2; sc[mf][nf][3] = p3;
            }

        // --- store P into this warp's private Ps rows ---
        #pragma unroll
        for (int mf = 0; mf < 2; ++mf) {
            int rr = warp * 32 + mf * 16 + g;
            #pragma unroll
            for (int nf = 0; nf < 8; ++nf) {
                *(float2*)&Ps[rr    ][nf * 8 + 2 * t] =
                    make_float2(f2tf_f(sc[mf][nf][0]), f2tf_f(sc[mf][nf][1]));
                *(float2*)&Ps[rr + 8][nf * 8 + 2 * t] =
                    make_float2(f2tf_f(sc[mf][nf][2]), f2tf_f(sc[mf][nf][3]));
            }
        }
        __syncwarp();

        // --- O += P @ V ---
        #pragma unroll
        for (int s = 0; s < 8; ++s) {
            uint32_t pa[2][4];
            #pragma unroll
            for (int mf = 0; mf < 2; ++mf) {
                int rr = warp * 32 + mf * 16;
                pa[mf][0] = __float_as_uint(Ps[rr + g    ][s * 8 + t    ]);
                pa[mf][1] = __float_as_uint(Ps[rr + g + 8][s * 8 + t    ]);
                pa[mf][2] = __float_as_uint(Ps[rr + g    ][s * 8 + t + 4]);
                pa[mf][3] = __float_as_uint(Ps[rr + g + 8][s * 8 + t + 4]);
            }
            #pragma unroll
            for (int nf = 0; nf < 8; ++nf) {
                uint32_t b0 = __float_as_uint(Vs[s * 8 + t    ][nf * 8 + g]);
                uint32_t b1 = __float_as_uint(Vs[s * 8 + t + 4][nf * 8 + g]);
                mma8(o[0][nf][0], o[0][nf][1], o[0][nf][2], o[0][nf][3],
                     pa[0][0], pa[0][1], pa[0][2], pa[0][3], b0, b1);
                mma8(o[1][nf][0], o[1][nf][1], o[1][nf][2], o[1][nf][3],
                     pa[1][0], pa[1][1], pa[1][2], pa[1][3], b0, b1);
            }
        }
    }

    // --- finalize ---
    #pragma unroll
    for (int rix = 0; rix < 4; ++rix) {
        lr[rix] += __shfl_xor_sync(0xffffffffu, lr[rix], 1);
        lr[rix] += __shfl_xor_sync(0xffffffffu, lr[rix], 2);
        lr[rix] = 1.f / lr[rix];
    }
    #pragma unroll
    for (int mf = 0; mf < 2; ++mf) {
        float* Og = g_ao + ((size_t)bh * T_ + rbase + mf * 16 + g) * D_;
        #pragma unroll
        for (int nf = 0; nf < 8; ++nf) {
            *(float2*)(Og + nf * 8 + 2 * t) =
                make_float2(o[mf][nf][0] * lr[mf * 2 + 0],
                            o[mf][nf][1] * lr[mf * 2 + 0]);
            *(float2*)(Og + 8 * D_ + nf * 8 + 2 * t) =
                make_float2(o[mf][nf][2] * lr[mf * 2 + 1],
                            o[mf][nf][3] * lr[mf * 2 + 1]);
        }
    }
}

// ---------------------------------------------------------------------------
extern "C" void kernel_launch(void* const* d_in, const int* in_sizes, int n_in,
                              void* d_out, int out_size) {
    const float* x  = (const float*)d_in[0];
    const float* Wq = (const float*)d_in[1];
    const float* Wk = (const float*)d_in[2];
    const float* Wv = (const float*)d_in[3];
    const float* Wo = (const float*)d_in[4];
    float* out = (float*)d_out;

    cudaFuncSetAttribute(attn_tf32, cudaFuncAttributeMaxDynamicSharedMemorySize,
                         ATTN_SMEM);

    dim3 gg(INNER_ / 128, (B_ * T_) / 128);   // 8 x 64
    mm_tf32<<<gg, 256>>>(x, Wq, nullptr, 0, KPROJ);
    mm_tf32<<<gg, 256>>>(x, Wk, nullptr, 1, KPROJ);
    mm_tf32<<<gg, 256>>>(x, Wv, nullptr, 2, KPROJ);
    attn_tf32<<<dim3(T_ / 128, B_ * H_), 128, ATTN_SMEM>>>();
    mm_tf32<<<gg, 256>>>(x /*unused*/, Wo, out, 3, INNER_);
}

// round 7
// speedup vs baseline: 6.6960x; 1.9498x over previous
#include <cuda_runtime.h>
#include <cuda_fp16.h>
#include <cstdint>

#define B_     4
#define T_     2048
#define H_     16
#define D_     64
#define INNER_ 1024
#define DM_    1024
#define KPROJ  512

// Scratch. q/k/v in fp16 (same 11-bit mantissa as the tf32 path had);
// attention output kept fp32 to protect the error budget.
__device__ __half g_q [(size_t)B_*H_*T_*D_];
__device__ __half g_k [(size_t)B_*H_*T_*D_];
__device__ __half g_v [(size_t)B_*H_*T_*D_];
__device__ float  g_ao[(size_t)B_*H_*T_*D_];

// ---------------------------------------------------------------------------
// helpers
// ---------------------------------------------------------------------------
__device__ __forceinline__ uint32_t f22h2(float lo, float hi) {
    __half2 h = __floats2half2_rn(lo, hi);   // .x = lo (low 16 bits)
    return *reinterpret_cast<uint32_t*>(&h);
}
__device__ __forceinline__ void mma16(float& c0, float& c1, float& c2, float& c3,
                                      uint32_t a0, uint32_t a1, uint32_t a2, uint32_t a3,
                                      uint32_t b0, uint32_t b1) {
    asm volatile(
        "mma.sync.aligned.m16n8k16.row.col.f32.f16.f16.f32 "
        "{%0,%1,%2,%3},{%4,%5,%6,%7},{%8,%9},{%0,%1,%2,%3};"
        : "+f"(c0), "+f"(c1), "+f"(c2), "+f"(c3)
        : "r"(a0), "r"(a1), "r"(a2), "r"(a3), "r"(b0), "r"(b1));
}

// ---------------------------------------------------------------------------
// fp16 GEMM. mode: 0=Q proj, 1=K proj, 2=V proj (A = slice of x, fp32 in gmem,
// epilogue stores __half to g_q/g_k/g_v), 3 = output GEMM (A = g_ao fp32
// gathered, epilogue stores fp32 to d_out).
// BM=128, BN=128, BK=32, 256 thr; 8 warps 4(m)x2(n); warp tile 32x64.
// Smem words: As[m][kpair] (A-frag native), Bs[kpair][n] (B-frag native).
// ---------------------------------------------------------------------------
__global__ __launch_bounds__(256) void mm_f16(const float* __restrict__ A,
                                              const float* __restrict__ W,
                                              float* __restrict__ Cout,
                                              int mode, int Ktot) {
    __shared__ uint32_t As[128][20];   // stride 20 -> banks (20g+t) bijective
    __shared__ uint32_t Bs[16][136];   // stride 136 -> banks 8t+g

    const int tid  = threadIdx.x;
    const int warp = tid >> 5, lane = tid & 31;
    const int g = lane >> 2, t = lane & 3;
    const int wm = warp >> 1, wn = warp & 1;
    const int m0 = blockIdx.y * 128, n0 = blockIdx.x * 128;
    const int coloff = (mode == 2) ? 0 : 512;

    float c[2][8][4];
    #pragma unroll
    for (int mf = 0; mf < 2; ++mf)
        #pragma unroll
        for (int nf = 0; nf < 8; ++nf)
            #pragma unroll
            for (int e = 0; e < 4; ++e) c[mf][nf][e] = 0.f;

    for (int k0 = 0; k0 < Ktot; k0 += 32) {
        // --- stage A (128x32 halves = 128x16 words), cvt fp32->fp16 ---
        #pragma unroll
        for (int i = 0; i < 4; ++i) {
            int idx = tid + 256 * i;
            int r = idx >> 3, c4 = idx & 7;          // c4: float4 group in k
            const float* src;
            if (mode < 3) {
                src = A + (size_t)(m0 + r) * DM_ + coloff + k0 + c4 * 4;
            } else {
                int m = m0 + r, b = m >> 11, tt = m & (T_ - 1);
                int k = k0 + c4 * 4, h = k >> 6, d = k & 63;
                src = g_ao + (((size_t)b * H_ + h) * T_ + tt) * D_ + d;
            }
            float4 v = *(const float4*)src;
            *(uint2*)&As[r][c4 * 2] =
                make_uint2(f22h2(v.x, v.y), f22h2(v.z, v.w));
        }
        // --- stage B (32x128): pack k-pairs into words ---
        #pragma unroll
        for (int i = 0; i < 2; ++i) {
            int idx = tid + 256 * i;
            int kp = idx >> 5, c4 = idx & 31;
            const float* w0 = W + (size_t)(k0 + 2 * kp) * 1024 + n0 + c4 * 4;
            float4 r0 = *(const float4*)w0;
            float4 r1 = *(const float4*)(w0 + 1024);
            *(uint4*)&Bs[kp][c4 * 4] =
                make_uint4(f22h2(r0.x, r1.x), f22h2(r0.y, r1.y),
                           f22h2(r0.z, r1.z), f22h2(r0.w, r1.w));
        }
        __syncthreads();

        #pragma unroll
        for (int s = 0; s < 2; ++s) {
            uint32_t a[2][4];
            #pragma unroll
            for (int mf = 0; mf < 2; ++mf) {
                int rr = wm * 32 + mf * 16;
                a[mf][0] = As[rr + g    ][s * 8 + t    ];
                a[mf][1] = As[rr + g + 8][s * 8 + t    ];
                a[mf][2] = As[rr + g    ][s * 8 + t + 4];
                a[mf][3] = As[rr + g + 8][s * 8 + t + 4];
            }
            #pragma unroll
            for (int nf = 0; nf < 8; ++nf) {
                int cc = wn * 64 + nf * 8 + g;
                uint32_t b0 = Bs[s * 8 + t    ][cc];
                uint32_t b1 = Bs[s * 8 + t + 4][cc];
                mma16(c[0][nf][0], c[0][nf][1], c[0][nf][2], c[0][nf][3],
                      a[0][0], a[0][1], a[0][2], a[0][3], b0, b1);
                mma16(c[1][nf][0], c[1][nf][1], c[1][nf][2], c[1][nf][3],
                      a[1][0], a[1][1], a[1][2], a[1][3], b0, b1);
            }
        }
        __syncthreads();
    }

    // --- epilogue ---
    if (mode < 3) {
        __half* outp = (mode == 0) ? g_q : (mode == 1) ? g_k : g_v;
        #pragma unroll
        for (int mf = 0; mf < 2; ++mf) {
            #pragma unroll
            for (int nf = 0; nf < 8; ++nf) {
                int col = n0 + wn * 64 + nf * 8 + 2 * t;
                int h = col >> 6, d = col & 63;
                int row = m0 + wm * 32 + mf * 16 + g;
                int b = row >> 11, tt = row & (T_ - 1);
                *(uint32_t*)(outp + (((size_t)b * H_ + h) * T_ + tt) * D_ + d) =
                    f22h2(c[mf][nf][0], c[mf][nf][1]);
                row += 8; b = row >> 11; tt = row & (T_ - 1);
                *(uint32_t*)(outp + (((size_t)b * H_ + h) * T_ + tt) * D_ + d) =
                    f22h2(c[mf][nf][2], c[mf][nf][3]);
            }
        }
    } else {
        #pragma unroll
        for (int mf = 0; mf < 2; ++mf) {
            #pragma unroll
            for (int nf = 0; nf < 8; ++nf) {
                int row = m0 + wm * 32 + mf * 16 + g;
                int cc  = n0 + wn * 64 + nf * 8 + 2 * t;
                *(float2*)(Cout + (size_t)row * DM_ + cc) =
                    make_float2(c[mf][nf][0], c[mf][nf][1]);
                *(float2*)(Cout + (size_t)(row + 8) * DM_ + cc) =
                    make_float2(c[mf][nf][2], c[mf][nf][3]);
            }
        }
    }
}

// ---------------------------------------------------------------------------
// Flash attention, fp16 mma. 128 queries/block, 4 warps, warp tile 32x64.
// Qs/Ks: natural [row][d-pair-word] layout (A-frag & col-major-B native).
// Vs: key-pair packed [kp][d] (B-frag for PV). P stays in registers: the
// S-mma C fragment IS the PV A fragment in fp16.
// ---------------------------------------------------------------------------
__global__ __launch_bounds__(128) void attn_f16() {
    __shared__ uint32_t Qs[128][36];  // 18KB; banks 4g+t
    __shared__ uint32_t Ks[64][36];   //  9KB; banks 4g+t
    __shared__ uint32_t Vs[32][72];   //  9KB; banks 8t+g

    const int tid = threadIdx.x, warp = tid >> 5, lane = tid & 31;
    const int g = lane >> 2, t = lane & 3;
    const int bh = blockIdx.y;
    const int qb = (gridDim.x - 1) - blockIdx.x;   // heavy blocks first
    const int q0 = qb * 128;
    const float scale = 0.125f;   // 1/sqrt(64)

    // --- stage Q (128 rows x 32 words), raw fp16 copy ---
    const uint32_t* Qg = (const uint32_t*)(g_q + ((size_t)bh * T_ + q0) * D_);
    #pragma unroll
    for (int i = 0; i < 8; ++i) {
        int idx = tid + 128 * i;
        int r = idx >> 3, w4 = idx & 7;
        *(uint4*)&Qs[r][w4 * 4] = *(const uint4*)(Qg + r * 32 + w4 * 4);
    }

    float o[2][8][4];
    #pragma unroll
    for (int mf = 0; mf < 2; ++mf)
        #pragma unroll
        for (int nf = 0; nf < 8; ++nf)
            #pragma unroll
            for (int e = 0; e < 4; ++e) o[mf][nf][e] = 0.f;
    float mr[4] = {-1e30f, -1e30f, -1e30f, -1e30f};
    float lr[4] = {0.f, 0.f, 0.f, 0.f};

    const int rbase = q0 + warp * 32;
    const int nkt = 2 * qb + 2;

    for (int kt = 0; kt < nkt; ++kt) {
        __syncthreads();   // prev-iter K/V reads done
        const uint32_t* Kg = (const uint32_t*)(g_k + ((size_t)bh * T_ + kt * 64) * D_);
        const uint32_t* Vg = (const uint32_t*)(g_v + ((size_t)bh * T_ + kt * 64) * D_);
        // K: raw word copy (64 x 32 words)
        #pragma unroll
        for (int i = 0; i < 4; ++i) {
            int idx = tid + 128 * i;
            int r = idx >> 3, w4 = idx & 7;
            *(uint4*)&Ks[r][w4 * 4] = *(const uint4*)(Kg + r * 32 + w4 * 4);
        }
        // V: pack key pairs -> Vs[kp][d]
        #pragma unroll
        for (int i = 0; i < 8; ++i) {
            int idx = tid + 128 * i;
            int dw = idx & 31, kp = idx >> 5;
            uint32_t w0 = Vg[(2 * kp    ) * 32 + dw];
            uint32_t w1 = Vg[(2 * kp + 1) * 32 + dw];
            *(uint2*)&Vs[kp][2 * dw] =
                make_uint2(__byte_perm(w0, w1, 0x5410),
                           __byte_perm(w0, w1, 0x7632));
        }
        __syncthreads();

        if (kt * 64 > rbase + 31) continue;   // fully-masked for this warp

        // --- S = Q @ K^T (32x64 per warp), fp32 accum ---
        float sc[2][8][4];
        #pragma unroll
        for (int mf = 0; mf < 2; ++mf)
            #pragma unroll
            for (int nf = 0; nf < 8; ++nf)
                #pragma unroll
                for (int e = 0; e < 4; ++e) sc[mf][nf][e] = 0.f;
        #pragma unroll
        for (int s = 0; s < 4; ++s) {
            uint32_t a[2][4];
            #pragma unroll
            for (int mf = 0; mf < 2; ++mf) {
                int rr = warp * 32 + mf * 16;
                a[mf][0] = Qs[rr + g    ][s * 8 + t    ];
                a[mf][1] = Qs[rr + g + 8][s * 8 + t    ];
                a[mf][2] = Qs[rr + g    ][s * 8 + t + 4];
                a[mf][3] = Qs[rr + g + 8][s * 8 + t + 4];
            }
            #pragma unroll
            for (int nf = 0; nf < 8; ++nf) {
                uint32_t b0 = Ks[nf * 8 + g][s * 8 + t    ];
                uint32_t b1 = Ks[nf * 8 + g][s * 8 + t + 4];
                mma16(sc[0][nf][0], sc[0][nf][1], sc[0][nf][2], sc[0][nf][3],
                      a[0][0], a[0][1], a[0][2], a[0][3], b0, b1);
                mma16(sc[1][nf][0], sc[1][nf][1], sc[1][nf][2], sc[1][nf][3],
                      a[1][0], a[1][1], a[1][2], a[1][3], b0, b1);
            }
        }
        #pragma unroll
        for (int mf = 0; mf < 2; ++mf)
            #pragma unroll
            for (int nf = 0; nf < 8; ++nf)
                #pragma unroll
                for (int e = 0; e < 4; ++e) sc[mf][nf][e] *= scale;

        // --- causal mask (boundary tiles) ---
        if (kt >= 2 * qb) {
            #pragma unroll
            for (int mf = 0; mf < 2; ++mf) {
                int row0 = rbase + mf * 16 + g;
                int row1 = row0 + 8;
                #pragma unroll
                for (int nf = 0; nf < 8; ++nf) {
                    int col = kt * 64 + nf * 8 + 2 * t;
                    if (col     > row0) sc[mf][nf][0] = -1e30f;
                    if (col + 1 > row0) sc[mf][nf][1] = -1e30f;
                    if (col     > row1) sc[mf][nf][2] = -1e30f;
                    if (col + 1 > row1) sc[mf][nf][3] = -1e30f;
                }
            }
        }

        // --- online softmax ---
        float mx[4] = {-1e30f, -1e30f, -1e30f, -1e30f};
        #pragma unroll
        for (int mf = 0; mf < 2; ++mf)
            #pragma unroll
            for (int nf = 0; nf < 8; ++nf) {
                mx[mf * 2 + 0] = fmaxf(mx[mf * 2 + 0], fmaxf(sc[mf][nf][0], sc[mf][nf][1]));
                mx[mf * 2 + 1] = fmaxf(mx[mf * 2 + 1], fmaxf(sc[mf][nf][2], sc[mf][nf][3]));
            }
        #pragma unroll
        for (int rix = 0; rix < 4; ++rix) {
            mx[rix] = fmaxf(mx[rix], __shfl_xor_sync(0xffffffffu, mx[rix], 1));
            mx[rix] = fmaxf(mx[rix], __shfl_xor_sync(0xffffffffu, mx[rix], 2));
        }
        float mn[4], cor[4];
        #pragma unroll
        for (int rix = 0; rix < 4; ++rix) {
            mn[rix]  = fmaxf(mr[rix], mx[rix]);
            cor[rix] = __expf(mr[rix] - mn[rix]);
            lr[rix] *= cor[rix];
            mr[rix]  = mn[rix];
        }
        #pragma unroll
        for (int mf = 0; mf < 2; ++mf)
            #pragma unroll
            for (int nf = 0; nf < 8; ++nf) {
                o[mf][nf][0] *= cor[mf * 2 + 0]; o[mf][nf][1] *= cor[mf * 2 + 0];
                o[mf][nf][2] *= cor[mf * 2 + 1]; o[mf][nf][3] *= cor[mf * 2 + 1];
            }
        #pragma unroll
        for (int mf = 0; mf < 2; ++mf)
            #pragma unroll
            for (int nf = 0; nf < 8; ++nf) {
                float p0 = __expf(sc[mf][nf][0] - mn[mf * 2 + 0]);
                float p1 = __expf(sc[mf][nf][1] - mn[mf * 2 + 0]);
                float p2 = __expf(sc[mf][nf][2] - mn[mf * 2 + 1]);
                float p3 = __expf(sc[mf][nf][3] - mn[mf * 2 + 1]);
                lr[mf * 2 + 0] += p0 + p1;
                lr[mf * 2 + 1] += p2 + p3;
                sc[mf][nf][0] = p0; sc[mf][nf][1] = p1;
                sc[mf][nf][2] = p2; sc[mf][nf][3] = p3;
            }

        // --- O += P @ V ; P fragments built directly from sc registers ---
        #pragma unroll
        for (int s = 0; s < 4; ++s) {
            uint32_t pa[2][4];
            #pragma unroll
            for (int mf = 0; mf < 2; ++mf) {
                pa[mf][0] = f22h2(sc[mf][2*s  ][0], sc[mf][2*s  ][1]);
                pa[mf][1] = f22h2(sc[mf][2*s  ][2], sc[mf][2*s  ][3]);
                pa[mf][2] = f22h2(sc[mf][2*s+1][0], sc[mf][2*s+1][1]);
                pa[mf][3] = f22h2(sc[mf][2*s+1][2], sc[mf][2*s+1][3]);
            }
            #pragma unroll
            for (int nf = 0; nf < 8; ++nf) {
                uint32_t b0 = Vs[s * 8 + t    ][nf * 8 + g];
                uint32_t b1 = Vs[s * 8 + t + 4][nf * 8 + g];
                mma16(o[0][nf][0], o[0][nf][1], o[0][nf][2], o[0][nf][3],
                      pa[0][0], pa[0][1], pa[0][2], pa[0][3], b0, b1);
                mma16(o[1][nf][0], o[1][nf][1], o[1][nf][2], o[1][nf][3],
                      pa[1][0], pa[1][1], pa[1][2], pa[1][3], b0, b1);
            }
        }
    }

    // --- finalize ---
    #pragma unroll
    for (int rix = 0; rix < 4; ++rix) {
        lr[rix] += __shfl_xor_sync(0xffffffffu, lr[rix], 1);
        lr[rix] += __shfl_xor_sync(0xffffffffu, lr[rix], 2);
        lr[rix] = 1.f / lr[rix];
    }
    #pragma unroll
    for (int mf = 0; mf < 2; ++mf) {
        float* Og = g_ao + ((size_t)bh * T_ + rbase + mf * 16 + g) * D_;
        #pragma unroll
        for (int nf = 0; nf < 8; ++nf) {
            *(float2*)(Og + nf * 8 + 2 * t) =
                make_float2(o[mf][nf][0] * lr[mf * 2 + 0],
                            o[mf][nf][1] * lr[mf * 2 + 0]);
            *(float2*)(Og + 8 * D_ + nf * 8 + 2 * t) =
                make_float2(o[mf][nf][2] * lr[mf * 2 + 1],
                            o[mf][nf][3] * lr[mf * 2 + 1]);
        }
    }
}

// ---------------------------------------------------------------------------
extern "C" void kernel_launch(void* const* d_in, const int* in_sizes, int n_in,
                              void* d_out, int out_size) {
    const float* x  = (const float*)d_in[0];
    const float* Wq = (const float*)d_in[1];
    const float* Wk = (const float*)d_in[2];
    const float* Wv = (const float*)d_in[3];
    const float* Wo = (const float*)d_in[4];
    float* out = (float*)d_out;

    dim3 gg(INNER_ / 128, (B_ * T_) / 128);   // 8 x 64
    mm_f16<<<gg, 256>>>(x, Wq, nullptr, 0, KPROJ);
    mm_f16<<<gg, 256>>>(x, Wk, nullptr, 1, KPROJ);
    mm_f16<<<gg, 256>>>(x, Wv, nullptr, 2, KPROJ);
    attn_f16<<<dim3(T_ / 128, B_ * H_), 128>>>();
    mm_f16<<<gg, 256>>>(nullptr, Wo, out, 3, INNER_);
}

// round 8
// speedup vs baseline: 7.9603x; 1.1888x over previous
#include <cuda_runtime.h>
#include <cuda_fp16.h>
#include <cstdint>

#define B_     4
#define T_     2048
#define H_     16
#define D_     64
#define INNER_ 1024
#define DM_    1024
#define KPROJ  512

// ---------------- device scratch (no allocation) ----------------
__device__ __half    g_xh [(size_t)B_*T_*DM_];          // x in fp16
__device__ uint32_t  g_wq [(KPROJ/2)*INNER_];           // weights, k-pair packed words
__device__ uint32_t  g_wk [(KPROJ/2)*INNER_];
__device__ uint32_t  g_wv [(KPROJ/2)*INNER_];
__device__ uint32_t  g_wo [(INNER_/2)*DM_];
__device__ __half    g_q  [(size_t)B_*H_*T_*D_];
__device__ __half    g_k  [(size_t)B_*H_*T_*D_];
__device__ __half    g_v  [(size_t)B_*H_*T_*D_];
__device__ uint32_t  g_vp [(size_t)B_*H_*(T_/2)*D_];    // V key-pair packed words
__device__ __half    g_aoh[(size_t)B_*T_*INNER_];       // attn out, [b][t][h*64+d]

// ---------------- helpers ----------------
__device__ __forceinline__ uint32_t f22h2(float lo, float hi) {
    __half2 h = __floats2half2_rn(lo, hi);
    return *reinterpret_cast<uint32_t*>(&h);
}
__device__ __forceinline__ float ex2f(float x) {
    float r; asm("ex2.approx.f32 %0, %1;" : "=f"(r) : "f"(x)); return r;
}
__device__ __forceinline__ void mma16(float& c0, float& c1, float& c2, float& c3,
                                      uint32_t a0, uint32_t a1, uint32_t a2, uint32_t a3,
                                      uint32_t b0, uint32_t b1) {
    asm volatile(
        "mma.sync.aligned.m16n8k16.row.col.f32.f16.f16.f32 "
        "{%0,%1,%2,%3},{%4,%5,%6,%7},{%8,%9},{%0,%1,%2,%3};"
        : "+f"(c0), "+f"(c1), "+f"(c2), "+f"(c3)
        : "r"(a0), "r"(a1), "r"(a2), "r"(a3), "r"(b0), "r"(b1));
}
__device__ __forceinline__ void cpa16(void* dst, const void* src) {
    uint32_t d = (uint32_t)__cvta_generic_to_shared(dst);
    asm volatile("cp.async.cg.shared.global [%0], [%1], 16;" :: "r"(d), "l"(src));
}
#define CP_COMMIT asm volatile("cp.async.commit_group;")
#define CP_WAIT1  asm volatile("cp.async.wait_group 1;")
#define CP_WAIT0  asm volatile("cp.async.wait_group 0;")

// ---------------- prep: x -> fp16 ----------------
__global__ __launch_bounds__(256) void cvt_x(const float* __restrict__ x) {
    size_t i = ((size_t)blockIdx.x * 256 + threadIdx.x) * 8;
    float4 a = *(const float4*)(x + i);
    float4 b = *(const float4*)(x + i + 4);
    *(uint4*)((uint32_t*)g_xh + i / 2) =
        make_uint4(f22h2(a.x, a.y), f22h2(a.z, a.w),
                   f22h2(b.x, b.y), f22h2(b.z, b.w));
}

// ---------------- prep: weight -> fp16, k-pair packed ----------------
__global__ __launch_bounds__(256) void cvt_w(const float* __restrict__ W, int which) {
    uint32_t* base = (which == 0) ? g_wq : (which == 1) ? g_wk
                   : (which == 2) ? g_wv : g_wo;
    int idx = blockIdx.x * 256 + threadIdx.x;
    int kp = idx >> 8, c4 = idx & 255;           // 256 groups of 4 cols
    float4 r0 = *(const float4*)(W + (size_t)(2 * kp)     * INNER_ + c4 * 4);
    float4 r1 = *(const float4*)(W + (size_t)(2 * kp + 1) * INNER_ + c4 * 4);
    *(uint4*)(base + (size_t)kp * INNER_ + c4 * 4) =
        make_uint4(f22h2(r0.x, r1.x), f22h2(r0.y, r1.y),
                   f22h2(r0.z, r1.z), f22h2(r0.w, r1.w));
}

// ---------------- prep: pack V into key-pair words ----------------
__global__ __launch_bounds__(256) void pack_v() {
    int idx = blockIdx.x * 256 + threadIdx.x;      // 64*1024*8
    int w4 = idx & 7, kp = (idx >> 3) & 1023, bh = idx >> 13;
    const uint4* src = (const uint4*)(g_v + (size_t)bh * T_ * D_);
    uint4 a = src[(2 * kp)     * 8 + w4];
    uint4 b = src[(2 * kp + 1) * 8 + w4];
    uint32_t* dst = g_vp + ((size_t)bh * 1024 + kp) * 64 + w4 * 8;
    *(uint4*)dst = make_uint4(__byte_perm(a.x, b.x, 0x5410), __byte_perm(a.x, b.x, 0x7632),
                              __byte_perm(a.y, b.y, 0x5410), __byte_perm(a.y, b.y, 0x7632));
    *(uint4*)(dst + 4) = make_uint4(__byte_perm(a.z, b.z, 0x5410), __byte_perm(a.z, b.z, 0x7632),
                                    __byte_perm(a.w, b.w, 0x5410), __byte_perm(a.w, b.w, 0x7632));
}

// ---------------------------------------------------------------------------
// fp16 GEMM, cp.async double-buffered. mode: 0=Q,1=K,2=V proj, 3=out GEMM.
// BM=128, BN=128, BK=32, 256 thr; 8 warps 4(m)x2(n); warp tile 32x64.
// ---------------------------------------------------------------------------
__global__ __launch_bounds__(256, 2) void mm_f16(float* __restrict__ Cout,
                                                 int mode, int Ktot) {
    __shared__ uint32_t As[2][128][20];   // [m][k-word]; banks 20g+t bijective
    __shared__ uint32_t Bs[2][16][136];   // [kp][n];     banks 8t+g

    const __half*   Ah = (mode == 3) ? g_aoh : (g_xh + ((mode == 2) ? 0 : 512));
    const uint32_t* Wp = (mode == 0) ? g_wq : (mode == 1) ? g_wk
                       : (mode == 2) ? g_wv : g_wo;

    const int tid  = threadIdx.x;
    const int warp = tid >> 5, lane = tid & 31;
    const int g = lane >> 2, t = lane & 3;
    const int wm = warp >> 1, wn = warp & 1;
    const int m0 = blockIdx.y * 128, n0 = blockIdx.x * 128;

    float c[2][8][4];
    #pragma unroll
    for (int mf = 0; mf < 2; ++mf)
        #pragma unroll
        for (int nf = 0; nf < 8; ++nf)
            #pragma unroll
            for (int e = 0; e < 4; ++e) c[mf][nf][e] = 0.f;

    auto load_stage = [&](int k0, int st) {
        #pragma unroll
        for (int i = 0; i < 2; ++i) {
            int idx = tid + 256 * i;
            int r = idx >> 2, c4 = idx & 3;
            cpa16(&As[st][r][c4 * 4], Ah + (size_t)(m0 + r) * DM_ + k0 + c4 * 8);
        }
        #pragma unroll
        for (int i = 0; i < 2; ++i) {
            int idx = tid + 256 * i;
            int kp = idx >> 5, c4 = idx & 31;
            cpa16(&Bs[st][kp][c4 * 4], Wp + (size_t)((k0 >> 1) + kp) * INNER_ + n0 + c4 * 4);
        }
        CP_COMMIT;
    };

    load_stage(0, 0);
    const int nk = Ktot >> 5;
    for (int ki = 0; ki < nk; ++ki) {
        int st = ki & 1;
        if (ki + 1 < nk) { load_stage((ki + 1) << 5, st ^ 1); CP_WAIT1; }
        else             { CP_WAIT0; }
        __syncthreads();

        #pragma unroll
        for (int s = 0; s < 2; ++s) {
            uint32_t a[2][4];
            #pragma unroll
            for (int mf = 0; mf < 2; ++mf) {
                int rr = wm * 32 + mf * 16;
                a[mf][0] = As[st][rr + g    ][s * 8 + t    ];
                a[mf][1] = As[st][rr + g + 8][s * 8 + t    ];
                a[mf][2] = As[st][rr + g    ][s * 8 + t + 4];
                a[mf][3] = As[st][rr + g + 8][s * 8 + t + 4];
            }
            #pragma unroll
            for (int nf = 0; nf < 8; ++nf) {
                int cc = wn * 64 + nf * 8 + g;
                uint32_t b0 = Bs[st][s * 8 + t    ][cc];
                uint32_t b1 = Bs[st][s * 8 + t + 4][cc];
                mma16(c[0][nf][0], c[0][nf][1], c[0][nf][2], c[0][nf][3],
                      a[0][0], a[0][1], a[0][2], a[0][3], b0, b1);
                mma16(c[1][nf][0], c[1][nf][1], c[1][nf][2], c[1][nf][3],
                      a[1][0], a[1][1], a[1][2], a[1][3], b0, b1);
            }
        }
        __syncthreads();
    }

    // --- epilogue ---
    if (mode < 3) {
        __half* outp = (mode == 0) ? g_q : (mode == 1) ? g_k : g_v;
        #pragma unroll
        for (int mf = 0; mf < 2; ++mf) {
            #pragma unroll
            for (int nf = 0; nf < 8; ++nf) {
                int col = n0 + wn * 64 + nf * 8 + 2 * t;
                int h = col >> 6, d = col & 63;
                int row = m0 + wm * 32 + mf * 16 + g;
                int b = row >> 11, tt = row & (T_ - 1);
                *(uint32_t*)(outp + (((size_t)b * H_ + h) * T_ + tt) * D_ + d) =
                    f22h2(c[mf][nf][0], c[mf][nf][1]);
                row += 8; b = row >> 11; tt = row & (T_ - 1);
                *(uint32_t*)(outp + (((size_t)b * H_ + h) * T_ + tt) * D_ + d) =
                    f22h2(c[mf][nf][2], c[mf][nf][3]);
            }
        }
    } else {
        #pragma unroll
        for (int mf = 0; mf < 2; ++mf) {
            #pragma unroll
            for (int nf = 0; nf < 8; ++nf) {
                int row = m0 + wm * 32 + mf * 16 + g;
                int cc  = n0 + wn * 64 + nf * 8 + 2 * t;
                *(float2*)(Cout + (size_t)row * DM_ + cc) =
                    make_float2(c[mf][nf][0], c[mf][nf][1]);
                *(float2*)(Cout + (size_t)(row + 8) * DM_ + cc) =
                    make_float2(c[mf][nf][2], c[mf][nf][3]);
            }
        }
    }
}

// ---------------------------------------------------------------------------
// Flash attention, fp16 mma. 128 queries/block, 8 warps, warp tile 16x64.
// cp.async double-buffered K/V. Smem (dynamic): Qs[128][36] Ks[2][64][36]
// Vs[2][32][72] = 55296 B.
// ---------------------------------------------------------------------------
#define ATTN_SMEM ((128*36 + 2*64*36 + 2*32*72) * 4)
#define SCALE_LOG2E 0.18033688011112042f   // (1/8) * log2(e)

__global__ __launch_bounds__(256, 2) void attn_f16() {
    extern __shared__ uint32_t smw[];
    uint32_t (*Qs)[36]     = (uint32_t(*)[36])smw;
    uint32_t (*Ks)[64][36] = (uint32_t(*)[64][36])(smw + 128 * 36);
    uint32_t (*Vs)[32][72] = (uint32_t(*)[32][72])(smw + 128 * 36 + 2 * 64 * 36);

    const int tid = threadIdx.x, warp = tid >> 5, lane = tid & 31;
    const int g = lane >> 2, t = lane & 3;
    const int bh = blockIdx.y;
    const int qb = (gridDim.x - 1) - blockIdx.x;   // heavy blocks first
    const int q0 = qb * 128;

    // --- stage Q (128 x 32 words) once ---
    const uint4* Qg = (const uint4*)(g_q + ((size_t)bh * T_ + q0) * D_);
    #pragma unroll
    for (int i = 0; i < 4; ++i) {
        int idx = tid + 256 * i;
        int r = idx >> 3, w4 = idx & 7;
        *(uint4*)&Qs[r][w4 * 4] = Qg[idx];
    }

    auto load_kv = [&](int kt, int st) {
        const uint4* Kg = (const uint4*)(g_k + ((size_t)bh * T_ + kt * 64) * D_);
        #pragma unroll
        for (int i = 0; i < 2; ++i) {
            int idx = tid + 256 * i;
            int r = idx >> 3, w4 = idx & 7;
            cpa16(&Ks[st][r][w4 * 4], Kg + idx);
        }
        const uint4* Vg = (const uint4*)(g_vp + ((size_t)bh * (T_ / 2) + kt * 32) * D_);
        #pragma unroll
        for (int i = 0; i < 2; ++i) {
            int idx = tid + 256 * i;
            int kp = idx >> 4, u = idx & 15;
            cpa16(&Vs[st][kp][u * 4], Vg + idx);
        }
        CP_COMMIT;
    };

    float o[8][4];
    #pragma unroll
    for (int nf = 0; nf < 8; ++nf)
        #pragma unroll
        for (int e = 0; e < 4; ++e) o[nf][e] = 0.f;
    float mr[2] = {-1e30f, -1e30f}, lr[2] = {0.f, 0.f};

    const int rbase = q0 + warp * 16;   // this warp's 16 query rows
    const int nkt = 2 * qb + 2;

    load_kv(0, 0);
    for (int kt = 0; kt < nkt; ++kt) {
        int st = kt & 1;
        if (kt + 1 < nkt) { load_kv(kt + 1, st ^ 1); CP_WAIT1; }
        else              { CP_WAIT0; }
        __syncthreads();

        if (kt * 64 <= rbase + 15) {   // not fully masked for this warp
            // --- S = Q @ K^T (16x64) ---
            float sc[8][4];
            #pragma unroll
            for (int nf = 0; nf < 8; ++nf)
                #pragma unroll
                for (int e = 0; e < 4; ++e) sc[nf][e] = 0.f;
            #pragma unroll
            for (int s = 0; s < 4; ++s) {
                int rr = warp * 16;
                uint32_t a0 = Qs[rr + g    ][s * 8 + t    ];
                uint32_t a1 = Qs[rr + g + 8][s * 8 + t    ];
                uint32_t a2 = Qs[rr + g    ][s * 8 + t + 4];
                uint32_t a3 = Qs[rr + g + 8][s * 8 + t + 4];
                #pragma unroll
                for (int nf = 0; nf < 8; ++nf) {
                    uint32_t b0 = Ks[st][nf * 8 + g][s * 8 + t    ];
                    uint32_t b1 = Ks[st][nf * 8 + g][s * 8 + t + 4];
                    mma16(sc[nf][0], sc[nf][1], sc[nf][2], sc[nf][3],
                          a0, a1, a2, a3, b0, b1);
                }
            }
            #pragma unroll
            for (int nf = 0; nf < 8; ++nf)
                #pragma unroll
                for (int e = 0; e < 4; ++e) sc[nf][e] *= SCALE_LOG2E;

            // --- causal mask (boundary tiles) ---
            if (kt >= 2 * qb) {
                int row0 = rbase + g, row1 = row0 + 8;
                #pragma unroll
                for (int nf = 0; nf < 8; ++nf) {
                    int col = kt * 64 + nf * 8 + 2 * t;
                    if (col     > row0) sc[nf][0] = -1e30f;
                    if (col + 1 > row0) sc[nf][1] = -1e30f;
                    if (col     > row1) sc[nf][2] = -1e30f;
                    if (col + 1 > row1) sc[nf][3] = -1e30f;
                }
            }

            // --- online softmax (base-2) ---
            float mx[2] = {-1e30f, -1e30f};
            #pragma unroll
            for (int nf = 0; nf < 8; ++nf) {
                mx[0] = fmaxf(mx[0], fmaxf(sc[nf][0], sc[nf][1]));
                mx[1] = fmaxf(mx[1], fmaxf(sc[nf][2], sc[nf][3]));
            }
            #pragma unroll
            for (int rix = 0; rix < 2; ++rix) {
                mx[rix] = fmaxf(mx[rix], __shfl_xor_sync(0xffffffffu, mx[rix], 1));
                mx[rix] = fmaxf(mx[rix], __shfl_xor_sync(0xffffffffu, mx[rix], 2));
            }
            float mn[2], cor[2];
            #pragma unroll
            for (int rix = 0; rix < 2; ++rix) {
                mn[rix]  = fmaxf(mr[rix], mx[rix]);
                cor[rix] = ex2f(mr[rix] - mn[rix]);
                lr[rix] *= cor[rix];
                mr[rix]  = mn[rix];
            }
            #pragma unroll
            for (int nf = 0; nf < 8; ++nf) {
                o[nf][0] *= cor[0]; o[nf][1] *= cor[0];
                o[nf][2] *= cor[1]; o[nf][3] *= cor[1];
            }
            #pragma unroll
            for (int nf = 0; nf < 8; ++nf) {
                float p0 = ex2f(sc[nf][0] - mn[0]);
                float p1 = ex2f(sc[nf][1] - mn[0]);
                float p2 = ex2f(sc[nf][2] - mn[1]);
                float p3 = ex2f(sc[nf][3] - mn[1]);
                lr[0] += p0 + p1; lr[1] += p2 + p3;
                sc[nf][0] = p0; sc[nf][1] = p1;
                sc[nf][2] = p2; sc[nf][3] = p3;
            }

            // --- O += P @ V (P fragments straight from registers) ---
            #pragma unroll
            for (int s = 0; s < 4; ++s) {
                uint32_t pa0 = f22h2(sc[2*s  ][0], sc[2*s  ][1]);
                uint32_t pa1 = f22h2(sc[2*s  ][2], sc[2*s  ][3]);
                uint32_t pa2 = f22h2(sc[2*s+1][0], sc[2*s+1][1]);
                uint32_t pa3 = f22h2(sc[2*s+1][2], sc[2*s+1][3]);
                #pragma unroll
                for (int nf = 0; nf < 8; ++nf) {
                    uint32_t b0 = Vs[st][s * 8 + t    ][nf * 8 + g];
                    uint32_t b1 = Vs[st][s * 8 + t + 4][nf * 8 + g];
                    mma16(o[nf][0], o[nf][1], o[nf][2], o[nf][3],
                          pa0, pa1, pa2, pa3, b0, b1);
                }
            }
        }
        __syncthreads();   // all warps done with stage st before it reloads
    }

    // --- finalize ---
    #pragma unroll
    for (int rix = 0; rix < 2; ++rix) {
        lr[rix] += __shfl_xor_sync(0xffffffffu, lr[rix], 1);
        lr[rix] += __shfl_xor_sync(0xffffffffu, lr[rix], 2);
        lr[rix] = 1.f / lr[rix];
    }
    const int b = bh >> 4, h = bh & 15;
    uint32_t* d0 = (uint32_t*)(g_aoh + ((size_t)b * T_ + rbase + g    ) * INNER_ + h * 64);
    uint32_t* d1 = (uint32_t*)(g_aoh + ((size_t)b * T_ + rbase + g + 8) * INNER_ + h * 64);
    #pragma unroll
    for (int nf = 0; nf < 8; ++nf) {
        d0[nf * 4 + t] = f22h2(o[nf][0] * lr[0], o[nf][1] * lr[0]);
        d1[nf * 4 + t] = f22h2(o[nf][2] * lr[1], o[nf][3] * lr[1]);
    }
}

// ---------------------------------------------------------------------------
extern "C" void kernel_launch(void* const* d_in, const int* in_sizes, int n_in,
                              void* d_out, int out_size) {
    const float* x  = (const float*)d_in[0];
    const float* Wq = (const float*)d_in[1];
    const float* Wk = (const float*)d_in[2];
    const float* Wv = (const float*)d_in[3];
    const float* Wo = (const float*)d_in[4];
    float* out = (float*)d_out;

    cudaFuncSetAttribute(attn_f16, cudaFuncAttributeMaxDynamicSharedMemorySize,
                         ATTN_SMEM);

    cvt_x<<<(B_ * T_ * DM_) / (256 * 8), 256>>>(x);
    cvt_w<<<KPROJ / 2, 256>>>(Wq, 0);
    cvt_w<<<KPROJ / 2, 256>>>(Wk, 1);
    cvt_w<<<KPROJ / 2, 256>>>(Wv, 2);
    cvt_w<<<INNER_ / 2, 256>>>(Wo, 3);

    dim3 gg(INNER_ / 128, (B_ * T_) / 128);   // 8 x 64
    mm_f16<<<gg, 256>>>(nullptr, 0, KPROJ);
    mm_f16<<<gg, 256>>>(nullptr, 1, KPROJ);
    mm_f16<<<gg, 256>>>(nullptr, 2, KPROJ);
    pack_v<<<(B_ * H_ * (T_ / 2) * 8) / 256, 256>>>();
    attn_f16<<<dim3(T_ / 128, B_ * H_), 256, ATTN_SMEM>>>();
    mm_f16<<<gg, 256>>>(out, 3, INNER_);
}